// round 6
// baseline (speedup 1.0000x reference)
#include <cuda_runtime.h>

// ---------------------------------------------------------------------------
// MaxViT3D MHSA, tf32 tensor-core pipeline (round 6):
//   - attention fragment loads via ldmatrix.x4 (4x fewer smem instructions)
//   - operands pre-converted to tf32 bit patterns
//   - cp.async double-buffered tf32 GEMMs
//   - flash-style attention without online-max, ctx written as tf32 bits
// ---------------------------------------------------------------------------

#define NWIN 128
#define NT   343
#define NTP  352          // padded to 22*16
#define NTB  352          // bias row stride
#define D    256
#define H    8
#define DH   32

// scratch
__device__ float    g_qkv   [(size_t)NWIN * NT * (3 * D)];
__device__ unsigned g_ctx   [(size_t)NWIN * NT * D];        // tf32 bits
__device__ float    g_bias  [(size_t)H * NT * NTB];
__device__ unsigned g_xtf   [(size_t)NWIN * NT * D];        // x as tf32 bits
__device__ unsigned g_wqkvtf[(size_t)D * 3 * D];
__device__ unsigned g_wouttf[(size_t)D * D];

// ---------------------------------------------------------------------------
// helpers
// ---------------------------------------------------------------------------
__device__ __forceinline__ unsigned f2tf(float f) {
    unsigned r;
    asm("cvt.rna.tf32.f32 %0, %1;" : "=r"(r) : "f"(f));
    return r;
}

__device__ __forceinline__ void mma8(float* c, const unsigned* a, const unsigned* b) {
    asm volatile(
        "mma.sync.aligned.m16n8k8.row.col.f32.tf32.tf32.f32 "
        "{%0,%1,%2,%3},{%4,%5,%6,%7},{%8,%9},{%0,%1,%2,%3};"
        : "+f"(c[0]), "+f"(c[1]), "+f"(c[2]), "+f"(c[3])
        : "r"(a[0]), "r"(a[1]), "r"(a[2]), "r"(a[3]), "r"(b[0]), "r"(b[1]));
}

__device__ __forceinline__ unsigned smem_u32(const void* p) {
    unsigned r;
    asm("{.reg .u64 t; cvta.to.shared.u64 t, %1; cvt.u32.u64 %0, t;}"
        : "=r"(r) : "l"(p));
    return r;
}

__device__ __forceinline__ void ldsm4(unsigned& r0, unsigned& r1,
                                      unsigned& r2, unsigned& r3,
                                      unsigned addr) {
    asm volatile(
        "ldmatrix.sync.aligned.m8n8.x4.shared.b16 {%0,%1,%2,%3}, [%4];"
        : "=r"(r0), "=r"(r1), "=r"(r2), "=r"(r3) : "r"(addr));
}

__device__ __forceinline__ void cpa16(unsigned dst, const void* src) {
    asm volatile("cp.async.ca.shared.global [%0], [%1], 16;" :: "r"(dst), "l"(src));
}
#define CP_COMMIT() asm volatile("cp.async.commit_group;")
#define CP_WAIT0()  asm volatile("cp.async.wait_group 0;")

// ---------------------------------------------------------------------------
// fp32 -> tf32-bits conversion kernels
// ---------------------------------------------------------------------------
__device__ __forceinline__ void cvt_body(const float4* __restrict__ src,
                                         uint4* __restrict__ dst, int n4) {
    int i = blockIdx.x * blockDim.x + threadIdx.x;
    if (i < n4) {
        float4 v = src[i];
        uint4 o;
        o.x = f2tf(v.x); o.y = f2tf(v.y); o.z = f2tf(v.z); o.w = f2tf(v.w);
        dst[i] = o;
    }
}

__global__ void cvt_x_kernel(const float4* __restrict__ src) {
    cvt_body(src, (uint4*)g_xtf, NWIN * NT * D / 4);
}
__global__ void cvt_wqkv_kernel(const float4* __restrict__ src) {
    cvt_body(src, (uint4*)g_wqkvtf, D * 3 * D / 4);
}
__global__ void cvt_wout_kernel(const float4* __restrict__ src) {
    cvt_body(src, (uint4*)g_wouttf, D * D / 4);
}

// ---------------------------------------------------------------------------
// bias precompute (padded row stride NTB)
// ---------------------------------------------------------------------------
__global__ void bias_kernel(const float* __restrict__ table) {
    int idx = blockIdx.x * blockDim.x + threadIdx.x;
    const int total = H * NT * NTB;
    if (idx >= total) return;
    int h = idx / (NT * NTB);
    int r = idx - h * (NT * NTB);
    int i = r / NTB;
    int j = r - i * NTB;
    float v = 0.0f;
    if (j < NT) {
        int i1 = i / 49, i2 = (i / 7) % 7, i3 = i % 7;
        int j1 = j / 49, j2 = (j / 7) % 7, j3 = j % 7;
        int rel = ((i1 - j1 + 6) * 13 + (i2 - j2 + 6)) * 13 + (i3 - j3 + 6);
        v = table[rel * H + h];
    }
    g_bias[idx] = v;
}

// ---------------------------------------------------------------------------
// tf32 GEMM on pre-converted u32 operands (unchanged from round 5).
// ---------------------------------------------------------------------------
#define LA 20
#define LB 136

__device__ __forceinline__ void tf32_gemm_body(const unsigned* __restrict__ A,
                                               const unsigned* __restrict__ B,
                                               float* __restrict__ C,
                                               int N, int K) {
    __shared__ unsigned As[2][128 * LA];
    __shared__ unsigned Bs[2][16 * LB];

    const int tid  = threadIdx.x;
    const int warp = tid >> 5, lane = tid & 31;
    const int g = lane >> 2, t = lane & 3;
    const int wm = warp >> 2, wn = warp & 3;

    const int rowBase = blockIdx.y * 128;
    const int colBase = blockIdx.x * 128;

    float acc[4][4][4];
#pragma unroll
    for (int mt = 0; mt < 4; mt++)
#pragma unroll
        for (int nt = 0; nt < 4; nt++)
#pragma unroll
            for (int i = 0; i < 4; i++) acc[mt][nt][i] = 0.0f;

    auto loadTile = [&](int buf, int k0) {
#pragma unroll
        for (int i = 0; i < 2; i++) {
            int c = tid + i * 256;
            int row = c >> 2, q = (c & 3) * 4;
            cpa16(smem_u32(&As[buf][row * LA + q]),
                  A + (size_t)(rowBase + row) * K + k0 + q);
        }
#pragma unroll
        for (int i = 0; i < 2; i++) {
            int c = tid + i * 256;
            int row = c >> 5, col = (c & 31) * 4;
            cpa16(smem_u32(&Bs[buf][row * LB + col]),
                  B + (size_t)(k0 + row) * N + colBase + col);
        }
    };

    loadTile(0, 0);
    CP_COMMIT();

    const int iters = K / 16;
    for (int it = 0; it < iters; it++) {
        CP_WAIT0();
        __syncthreads();
        if (it + 1 < iters) {
            loadTile((it + 1) & 1, (it + 1) * 16);
            CP_COMMIT();
        }
        const unsigned* Ab = As[it & 1];
        const unsigned* Bb = Bs[it & 1];
#pragma unroll
        for (int ks = 0; ks < 16; ks += 8) {
            unsigned a[4][4], b[4][2];
#pragma unroll
            for (int mt = 0; mt < 4; mt++) {
                int r = wm * 64 + mt * 16;
                a[mt][0] = Ab[(r + g)     * LA + ks + t];
                a[mt][1] = Ab[(r + g + 8) * LA + ks + t];
                a[mt][2] = Ab[(r + g)     * LA + ks + t + 4];
                a[mt][3] = Ab[(r + g + 8) * LA + ks + t + 4];
            }
#pragma unroll
            for (int nt = 0; nt < 4; nt++) {
                int cb = wn * 32 + nt * 8;
                b[nt][0] = Bb[(ks + t)     * LB + cb + g];
                b[nt][1] = Bb[(ks + t + 4) * LB + cb + g];
            }
#pragma unroll
            for (int mt = 0; mt < 4; mt++)
#pragma unroll
                for (int nt = 0; nt < 4; nt++) mma8(acc[mt][nt], a[mt], b[nt]);
        }
    }

#pragma unroll
    for (int mt = 0; mt < 4; mt++) {
#pragma unroll
        for (int nt = 0; nt < 4; nt++) {
            int r = rowBase + wm * 64 + mt * 16 + g;
            int c = colBase + wn * 32 + nt * 8 + 2 * t;
            *(float2*)(C + (size_t)r * N + c) =
                make_float2(acc[mt][nt][0], acc[mt][nt][1]);
            *(float2*)(C + (size_t)(r + 8) * N + c) =
                make_float2(acc[mt][nt][2], acc[mt][nt][3]);
        }
    }
}

__global__ __launch_bounds__(256)
void k_gemm_qkv() {
    tf32_gemm_body(g_xtf, g_wqkvtf, g_qkv, 3 * D, D);
}

__global__ __launch_bounds__(256)
void k_gemm_out(float* __restrict__ out) {
    tf32_gemm_body(g_ctx, g_wouttf, out, D, D);
}

// ---------------------------------------------------------------------------
// attention: block = (window, head), 11 warps, 2 q-tiles/warp.
// Fragment loads via ldmatrix.x4.
// ---------------------------------------------------------------------------
#define LDKS 36
#define LDVT 356
#define LDP  20
#define AWARPS 11
#define ATHREADS (AWARPS * 32)

__global__ __launch_bounds__(ATHREADS, 2)
void attn_kernel() {
    const int win = blockIdx.x;
    const int h   = blockIdx.y;

    extern __shared__ unsigned sm[];
    unsigned* ks = sm;
    unsigned* vt = ks + NTP * LDKS;
    unsigned* ps = vt + 32 * LDVT;

    const int tid  = threadIdx.x;
    const int warp = tid >> 5, lane = tid & 31;
    const int g = lane >> 2, t = lane & 3;
    const int lrow = lane & 7;          // ldmatrix row within matrix
    const int lmat = lane >> 3;         // ldmatrix matrix index 0..3

    const float* base = g_qkv + (size_t)win * NT * (3 * D);

    for (int idx = tid; idx < NTP * DH; idx += ATHREADS) {
        int j = idx >> 5, c = idx & 31;
        float kv = 0.0f, vv = 0.0f;
        if (j < NT) {
            const float* row = base + (size_t)j * (3 * D) + h * DH;
            kv = row[D + c];
            vv = row[2 * D + c];
        }
        ks[j * LDKS + c] = f2tf(kv);
        vt[c * LDVT + j] = f2tf(vv);
    }
    __syncthreads();

    const float scale = 0.17677669529663687f;
    const float* bh = g_bias + (size_t)h * NT * NTB;
    unsigned* pw = ps + warp * 16 * LDP;

    // shared-space base addresses (bytes)
    const unsigned ks_b = smem_u32(ks);
    const unsigned vt_b = smem_u32(vt);
    const unsigned pw_b = smem_u32(pw);

    // per-lane invariant parts of ldmatrix addresses
    const unsigned ks_lane = ks_b + (lrow * LDKS + lmat * 4) * 4;
    const unsigned vt_lane = vt_b + (lrow * LDVT + lmat * 4) * 4;
    const unsigned pw_lane = pw_b + ((((lmat & 1) * 8 + lrow) * LDP)
                                     + (lmat >> 1) * 4) * 4;

    for (int qt = warp; qt < 22; qt += AWARPS) {
        const int i0 = qt * 16;
        const int r1 = i0 + g, r2 = r1 + 8;
        const int r1c = r1 < NT ? r1 : NT - 1;
        const int r2c = r2 < NT ? r2 : NT - 1;

        unsigned qa[4][4];
        const float* qp = base + h * DH;
#pragma unroll
        for (int kq = 0; kq < 4; kq++) {
            qa[kq][0] = f2tf(qp[(size_t)r1c * (3 * D) + kq * 8 + t]);
            qa[kq][1] = f2tf(qp[(size_t)r2c * (3 * D) + kq * 8 + t]);
            qa[kq][2] = f2tf(qp[(size_t)r1c * (3 * D) + kq * 8 + t + 4]);
            qa[kq][3] = f2tf(qp[(size_t)r2c * (3 * D) + kq * 8 + t + 4]);
        }

        float o[4][4];
#pragma unroll
        for (int ct = 0; ct < 4; ct++)
#pragma unroll
            for (int i = 0; i < 4; i++) o[ct][i] = 0.0f;
        float l1 = 0.0f, l2 = 0.0f;

        const float* b1p = bh + (size_t)r1c * NTB;
        const float* b2p = bh + (size_t)r2c * NTB;

        for (int cc = 0; cc < 22; cc++) {
            const int j0 = cc * 16;

            // ---- K b-frags: 4x ldmatrix.x4 (nt x kq-pair) ----
            unsigned kb[2][4][2];
#pragma unroll
            for (int nt = 0; nt < 2; nt++)
#pragma unroll
                for (int p = 0; p < 2; p++) {
                    unsigned addr = ks_lane
                        + ((j0 + nt * 8) * LDKS + p * 16) * 4;
                    ldsm4(kb[nt][2 * p][0], kb[nt][2 * p][1],
                          kb[nt][2 * p + 1][0], kb[nt][2 * p + 1][1], addr);
                }

            float s0[4] = {0, 0, 0, 0}, s1[4] = {0, 0, 0, 0};
#pragma unroll
            for (int kq = 0; kq < 4; kq++) {
                mma8(s0, qa[kq], kb[0][kq]);
                mma8(s1, qa[kq], kb[1][kq]);
            }

            // ---- V b-frags: 4x ldmatrix.x4 (independent of P) ----
            unsigned vb[4][2][2];
#pragma unroll
            for (int ct = 0; ct < 4; ct++) {
                unsigned addr = vt_lane + (ct * 8 * LDVT + j0) * 4;
                ldsm4(vb[ct][0][0], vb[ct][0][1],
                      vb[ct][1][0], vb[ct][1][1], addr);
            }

            // ---- bias + exp ----
            const int c0 = j0 + 2 * t;
            float2 b1a = *(const float2*)(b1p + c0);
            float2 b1b = *(const float2*)(b1p + c0 + 8);
            float2 b2a = *(const float2*)(b2p + c0);
            float2 b2b = *(const float2*)(b2p + c0 + 8);

            float p1[4], p2[4];
            p1[0] = (c0     < NT) ? __expf(fmaf(s0[0], scale, b1a.x)) : 0.0f;
            p1[1] = (c0 + 1 < NT) ? __expf(fmaf(s0[1], scale, b1a.y)) : 0.0f;
            p1[2] = (c0 + 8 < NT) ? __expf(fmaf(s1[0], scale, b1b.x)) : 0.0f;
            p1[3] = (c0 + 9 < NT) ? __expf(fmaf(s1[1], scale, b1b.y)) : 0.0f;
            p2[0] = (c0     < NT) ? __expf(fmaf(s0[2], scale, b2a.x)) : 0.0f;
            p2[1] = (c0 + 1 < NT) ? __expf(fmaf(s0[3], scale, b2a.y)) : 0.0f;
            p2[2] = (c0 + 8 < NT) ? __expf(fmaf(s1[2], scale, b2b.x)) : 0.0f;
            p2[3] = (c0 + 9 < NT) ? __expf(fmaf(s1[3], scale, b2b.y)) : 0.0f;

            l1 += p1[0] + p1[1] + p1[2] + p1[3];
            l2 += p2[0] + p2[1] + p2[2] + p2[3];

            // ---- publish P chunk: 4x STS.64 ----
            *(uint2*)&pw[g * LDP + 2 * t] =
                make_uint2(f2tf(p1[0]), f2tf(p1[1]));
            *(uint2*)&pw[g * LDP + 2 * t + 8] =
                make_uint2(f2tf(p1[2]), f2tf(p1[3]));
            *(uint2*)&pw[(g + 8) * LDP + 2 * t] =
                make_uint2(f2tf(p2[0]), f2tf(p2[1]));
            *(uint2*)&pw[(g + 8) * LDP + 2 * t + 8] =
                make_uint2(f2tf(p2[2]), f2tf(p2[3]));
            __syncwarp();

            // ---- P a-frags: 2x ldmatrix.x4 ----
            unsigned pa[2][4];
#pragma unroll
            for (int k2 = 0; k2 < 2; k2++) {
                unsigned addr = pw_lane + (k2 * 8) * 4;
                ldsm4(pa[k2][0], pa[k2][1], pa[k2][2], pa[k2][3], addr);
            }

            // ---- PV mma ----
#pragma unroll
            for (int k2 = 0; k2 < 2; k2++)
#pragma unroll
                for (int ct = 0; ct < 4; ct++)
                    mma8(o[ct], pa[k2], vb[ct][k2]);
            __syncwarp();
        }

        l1 += __shfl_xor_sync(0xffffffffu, l1, 1);
        l1 += __shfl_xor_sync(0xffffffffu, l1, 2);
        l2 += __shfl_xor_sync(0xffffffffu, l2, 1);
        l2 += __shfl_xor_sync(0xffffffffu, l2, 2);
        const float inv1 = 1.0f / l1;
        const float inv2 = 1.0f / l2;

        if (r1 < NT) {
            unsigned* c1 = g_ctx + ((size_t)win * NT + r1) * D + h * DH;
#pragma unroll
            for (int ct = 0; ct < 4; ct++) {
                c1[ct * 8 + 2 * t]     = f2tf(o[ct][0] * inv1);
                c1[ct * 8 + 2 * t + 1] = f2tf(o[ct][1] * inv1);
            }
        }
        if (r2 < NT) {
            unsigned* c2 = g_ctx + ((size_t)win * NT + r2) * D + h * DH;
#pragma unroll
            for (int ct = 0; ct < 4; ct++) {
                c2[ct * 8 + 2 * t]     = f2tf(o[ct][2] * inv2);
                c2[ct * 8 + 2 * t + 1] = f2tf(o[ct][3] * inv2);
            }
        }
    }
}

// ---------------------------------------------------------------------------
// launch
// ---------------------------------------------------------------------------
extern "C" void kernel_launch(void* const* d_in, const int* in_sizes, int n_in,
                              void* d_out, int out_size) {
    const float* x     = (const float*)d_in[0];
    const float* w_qkv = (const float*)d_in[1];
    const float* w_out = (const float*)d_in[2];
    const float* table = (const float*)d_in[3];
    float* out = (float*)d_out;

    {
        int n4x = NWIN * NT * D / 4;
        cvt_x_kernel<<<(n4x + 255) / 256, 256>>>((const float4*)x);
        int n4q = D * 3 * D / 4;
        cvt_wqkv_kernel<<<(n4q + 255) / 256, 256>>>((const float4*)w_qkv);
        int n4o = D * D / 4;
        cvt_wout_kernel<<<(n4o + 255) / 256, 256>>>((const float4*)w_out);
    }
    {
        int total = H * NT * NTB;
        bias_kernel<<<(total + 255) / 256, 256>>>(table);
    }
    {
        dim3 grid(3 * D / 128, (NWIN * NT) / 128);   // (6, 343)
        k_gemm_qkv<<<grid, 256>>>();
    }
    {
        const int smem = (NTP * LDKS + 32 * LDVT + AWARPS * 16 * LDP)
                         * (int)sizeof(unsigned);
        static int configured = -1;
        if (configured < 0) {
            cudaFuncSetAttribute(attn_kernel,
                                 cudaFuncAttributeMaxDynamicSharedMemorySize, smem);
            configured = 1;
        }
        dim3 grid(NWIN, H);
        attn_kernel<<<grid, ATHREADS, smem>>>();
    }
    {
        dim3 grid(D / 128, (NWIN * NT) / 128);       // (2, 343)
        k_gemm_out<<<grid, 256>>>(out);
    }
}

// round 7
// speedup vs baseline: 1.0480x; 1.0480x over previous
#include <cuda_runtime.h>

// ---------------------------------------------------------------------------
// MaxViT3D MHSA, tf32 tensor-core pipeline (round 7):
//   - attention ldmatrix.x4 fragment loads, liveness-ordered to avoid spills
//     under the 2-CTA/SM register cap (round-6 bug: vb hoist + reg cap spilled)
//   - operands pre-converted to tf32 bit patterns
//   - cp.async double-buffered tf32 GEMMs
// ---------------------------------------------------------------------------

#define NWIN 128
#define NT   343
#define NTP  352
#define NTB  352
#define D    256
#define H    8
#define DH   32

__device__ float    g_qkv   [(size_t)NWIN * NT * (3 * D)];
__device__ unsigned g_ctx   [(size_t)NWIN * NT * D];        // tf32 bits
__device__ float    g_bias  [(size_t)H * NT * NTB];
__device__ unsigned g_xtf   [(size_t)NWIN * NT * D];
__device__ unsigned g_wqkvtf[(size_t)D * 3 * D];
__device__ unsigned g_wouttf[(size_t)D * D];

// ---------------------------------------------------------------------------
// helpers
// ---------------------------------------------------------------------------
__device__ __forceinline__ unsigned f2tf(float f) {
    unsigned r;
    asm("cvt.rna.tf32.f32 %0, %1;" : "=r"(r) : "f"(f));
    return r;
}

__device__ __forceinline__ void mma8(float* c, const unsigned* a, const unsigned* b) {
    asm volatile(
        "mma.sync.aligned.m16n8k8.row.col.f32.tf32.tf32.f32 "
        "{%0,%1,%2,%3},{%4,%5,%6,%7},{%8,%9},{%0,%1,%2,%3};"
        : "+f"(c[0]), "+f"(c[1]), "+f"(c[2]), "+f"(c[3])
        : "r"(a[0]), "r"(a[1]), "r"(a[2]), "r"(a[3]), "r"(b[0]), "r"(b[1]));
}

__device__ __forceinline__ unsigned smem_u32(const void* p) {
    unsigned r;
    asm("{.reg .u64 t; cvta.to.shared.u64 t, %1; cvt.u32.u64 %0, t;}"
        : "=r"(r) : "l"(p));
    return r;
}

__device__ __forceinline__ void ldsm4(unsigned& r0, unsigned& r1,
                                      unsigned& r2, unsigned& r3,
                                      unsigned addr) {
    asm volatile(
        "ldmatrix.sync.aligned.m8n8.x4.shared.b16 {%0,%1,%2,%3}, [%4];"
        : "=r"(r0), "=r"(r1), "=r"(r2), "=r"(r3) : "r"(addr));
}

__device__ __forceinline__ void cpa16(unsigned dst, const void* src) {
    asm volatile("cp.async.ca.shared.global [%0], [%1], 16;" :: "r"(dst), "l"(src));
}
#define CP_COMMIT() asm volatile("cp.async.commit_group;")
#define CP_WAIT0()  asm volatile("cp.async.wait_group 0;")

// ---------------------------------------------------------------------------
// fp32 -> tf32-bits conversion kernels
// ---------------------------------------------------------------------------
__device__ __forceinline__ void cvt_body(const float4* __restrict__ src,
                                         uint4* __restrict__ dst, int n4) {
    int i = blockIdx.x * blockDim.x + threadIdx.x;
    if (i < n4) {
        float4 v = src[i];
        uint4 o;
        o.x = f2tf(v.x); o.y = f2tf(v.y); o.z = f2tf(v.z); o.w = f2tf(v.w);
        dst[i] = o;
    }
}

__global__ void cvt_x_kernel(const float4* __restrict__ src) {
    cvt_body(src, (uint4*)g_xtf, NWIN * NT * D / 4);
}
__global__ void cvt_wqkv_kernel(const float4* __restrict__ src) {
    cvt_body(src, (uint4*)g_wqkvtf, D * 3 * D / 4);
}
__global__ void cvt_wout_kernel(const float4* __restrict__ src) {
    cvt_body(src, (uint4*)g_wouttf, D * D / 4);
}

// ---------------------------------------------------------------------------
// bias precompute
// ---------------------------------------------------------------------------
__global__ void bias_kernel(const float* __restrict__ table) {
    int idx = blockIdx.x * blockDim.x + threadIdx.x;
    const int total = H * NT * NTB;
    if (idx >= total) return;
    int h = idx / (NT * NTB);
    int r = idx - h * (NT * NTB);
    int i = r / NTB;
    int j = r - i * NTB;
    float v = 0.0f;
    if (j < NT) {
        int i1 = i / 49, i2 = (i / 7) % 7, i3 = i % 7;
        int j1 = j / 49, j2 = (j / 7) % 7, j3 = j % 7;
        int rel = ((i1 - j1 + 6) * 13 + (i2 - j2 + 6)) * 13 + (i3 - j3 + 6);
        v = table[rel * H + h];
    }
    g_bias[idx] = v;
}

// ---------------------------------------------------------------------------
// tf32 GEMM (unchanged from round 5)
// ---------------------------------------------------------------------------
#define LA 20
#define LB 136

__device__ __forceinline__ void tf32_gemm_body(const unsigned* __restrict__ A,
                                               const unsigned* __restrict__ B,
                                               float* __restrict__ C,
                                               int N, int K) {
    __shared__ unsigned As[2][128 * LA];
    __shared__ unsigned Bs[2][16 * LB];

    const int tid  = threadIdx.x;
    const int warp = tid >> 5, lane = tid & 31;
    const int g = lane >> 2, t = lane & 3;
    const int wm = warp >> 2, wn = warp & 3;

    const int rowBase = blockIdx.y * 128;
    const int colBase = blockIdx.x * 128;

    float acc[4][4][4];
#pragma unroll
    for (int mt = 0; mt < 4; mt++)
#pragma unroll
        for (int nt = 0; nt < 4; nt++)
#pragma unroll
            for (int i = 0; i < 4; i++) acc[mt][nt][i] = 0.0f;

    auto loadTile = [&](int buf, int k0) {
#pragma unroll
        for (int i = 0; i < 2; i++) {
            int c = tid + i * 256;
            int row = c >> 2, q = (c & 3) * 4;
            cpa16(smem_u32(&As[buf][row * LA + q]),
                  A + (size_t)(rowBase + row) * K + k0 + q);
        }
#pragma unroll
        for (int i = 0; i < 2; i++) {
            int c = tid + i * 256;
            int row = c >> 5, col = (c & 31) * 4;
            cpa16(smem_u32(&Bs[buf][row * LB + col]),
                  B + (size_t)(k0 + row) * N + colBase + col);
        }
    };

    loadTile(0, 0);
    CP_COMMIT();

    const int iters = K / 16;
    for (int it = 0; it < iters; it++) {
        CP_WAIT0();
        __syncthreads();
        if (it + 1 < iters) {
            loadTile((it + 1) & 1, (it + 1) * 16);
            CP_COMMIT();
        }
        const unsigned* Ab = As[it & 1];
        const unsigned* Bb = Bs[it & 1];
#pragma unroll
        for (int ks = 0; ks < 16; ks += 8) {
            unsigned a[4][4], b[4][2];
#pragma unroll
            for (int mt = 0; mt < 4; mt++) {
                int r = wm * 64 + mt * 16;
                a[mt][0] = Ab[(r + g)     * LA + ks + t];
                a[mt][1] = Ab[(r + g + 8) * LA + ks + t];
                a[mt][2] = Ab[(r + g)     * LA + ks + t + 4];
                a[mt][3] = Ab[(r + g + 8) * LA + ks + t + 4];
            }
#pragma unroll
            for (int nt = 0; nt < 4; nt++) {
                int cb = wn * 32 + nt * 8;
                b[nt][0] = Bb[(ks + t)     * LB + cb + g];
                b[nt][1] = Bb[(ks + t + 4) * LB + cb + g];
            }
#pragma unroll
            for (int mt = 0; mt < 4; mt++)
#pragma unroll
                for (int nt = 0; nt < 4; nt++) mma8(acc[mt][nt], a[mt], b[nt]);
        }
    }

#pragma unroll
    for (int mt = 0; mt < 4; mt++) {
#pragma unroll
        for (int nt = 0; nt < 4; nt++) {
            int r = rowBase + wm * 64 + mt * 16 + g;
            int c = colBase + wn * 32 + nt * 8 + 2 * t;
            *(float2*)(C + (size_t)r * N + c) =
                make_float2(acc[mt][nt][0], acc[mt][nt][1]);
            *(float2*)(C + (size_t)(r + 8) * N + c) =
                make_float2(acc[mt][nt][2], acc[mt][nt][3]);
        }
    }
}

__global__ __launch_bounds__(256)
void k_gemm_qkv() {
    tf32_gemm_body(g_xtf, g_wqkvtf, g_qkv, 3 * D, D);
}

__global__ __launch_bounds__(256)
void k_gemm_out(float* __restrict__ out) {
    tf32_gemm_body(g_ctx, g_wouttf, out, D, D);
}

// ---------------------------------------------------------------------------
// attention: block = (window, head), 11 warps, ldmatrix fragment loads,
// liveness-ordered (K-frags die before V-frags are born; V loaded 2 tiles
// at a time) so 2 CTAs/SM compile without spills.
// ---------------------------------------------------------------------------
#define LDKS 36
#define LDVT 356
#define LDP  20
#define AWARPS 11
#define ATHREADS (AWARPS * 32)

__global__ __launch_bounds__(ATHREADS, 2)
void attn_kernel() {
    const int win = blockIdx.x;
    const int h   = blockIdx.y;

    extern __shared__ unsigned sm[];
    unsigned* ks = sm;
    unsigned* vt = ks + NTP * LDKS;
    unsigned* ps = vt + 32 * LDVT;

    const int tid  = threadIdx.x;
    const int warp = tid >> 5, lane = tid & 31;
    const int g = lane >> 2, t = lane & 3;
    const int lrow = lane & 7;
    const int lmat = lane >> 3;

    const float* base = g_qkv + (size_t)win * NT * (3 * D);

    for (int idx = tid; idx < NTP * DH; idx += ATHREADS) {
        int j = idx >> 5, c = idx & 31;
        float kv = 0.0f, vv = 0.0f;
        if (j < NT) {
            const float* row = base + (size_t)j * (3 * D) + h * DH;
            kv = row[D + c];
            vv = row[2 * D + c];
        }
        ks[j * LDKS + c] = f2tf(kv);
        vt[c * LDVT + j] = f2tf(vv);
    }
    __syncthreads();

    const float scale = 0.17677669529663687f;
    const float* bh = g_bias + (size_t)h * NT * NTB;
    unsigned* pw = ps + warp * 16 * LDP;

    const unsigned ks_lane = smem_u32(ks) + (lrow * LDKS + lmat * 4) * 4;
    const unsigned vt_lane = smem_u32(vt) + (lrow * LDVT + lmat * 4) * 4;
    const unsigned pw_lane = smem_u32(pw) + ((((lmat & 1) * 8 + lrow) * LDP)
                                             + (lmat >> 1) * 4) * 4;

    for (int qt = warp; qt < 22; qt += AWARPS) {
        const int i0 = qt * 16;
        const int r1 = i0 + g, r2 = r1 + 8;
        const int r1c = r1 < NT ? r1 : NT - 1;
        const int r2c = r2 < NT ? r2 : NT - 1;

        unsigned qa[4][4];
        const float* qp = base + h * DH;
#pragma unroll
        for (int kq = 0; kq < 4; kq++) {
            qa[kq][0] = f2tf(qp[(size_t)r1c * (3 * D) + kq * 8 + t]);
            qa[kq][1] = f2tf(qp[(size_t)r2c * (3 * D) + kq * 8 + t]);
            qa[kq][2] = f2tf(qp[(size_t)r1c * (3 * D) + kq * 8 + t + 4]);
            qa[kq][3] = f2tf(qp[(size_t)r2c * (3 * D) + kq * 8 + t + 4]);
        }

        float o[4][4];
#pragma unroll
        for (int ct = 0; ct < 4; ct++)
#pragma unroll
            for (int i = 0; i < 4; i++) o[ct][i] = 0.0f;
        float l1 = 0.0f, l2 = 0.0f;

        const float* b1p = bh + (size_t)r1c * NTB;
        const float* b2p = bh + (size_t)r2c * NTB;

        for (int cc = 0; cc < 22; cc++) {
            const int j0 = cc * 16;

            // ---- K b-frags (die at the QK mma below) ----
            float s0[4] = {0, 0, 0, 0}, s1[4] = {0, 0, 0, 0};
            {
                unsigned kb[2][4][2];
#pragma unroll
                for (int nt = 0; nt < 2; nt++)
#pragma unroll
                    for (int p = 0; p < 2; p++) {
                        unsigned addr = ks_lane
                            + ((j0 + nt * 8) * LDKS + p * 16) * 4;
                        ldsm4(kb[nt][2 * p][0], kb[nt][2 * p][1],
                              kb[nt][2 * p + 1][0], kb[nt][2 * p + 1][1], addr);
                    }
#pragma unroll
                for (int kq = 0; kq < 4; kq++) {
                    mma8(s0, qa[kq], kb[0][kq]);
                    mma8(s1, qa[kq], kb[1][kq]);
                }
            }

            // ---- bias + exp ----
            const int c0 = j0 + 2 * t;
            float2 b1a = *(const float2*)(b1p + c0);
            float2 b1b = *(const float2*)(b1p + c0 + 8);
            float2 b2a = *(const float2*)(b2p + c0);
            float2 b2b = *(const float2*)(b2p + c0 + 8);

            float p1[4], p2[4];
            p1[0] = (c0     < NT) ? __expf(fmaf(s0[0], scale, b1a.x)) : 0.0f;
            p1[1] = (c0 + 1 < NT) ? __expf(fmaf(s0[1], scale, b1a.y)) : 0.0f;
            p1[2] = (c0 + 8 < NT) ? __expf(fmaf(s1[0], scale, b1b.x)) : 0.0f;
            p1[3] = (c0 + 9 < NT) ? __expf(fmaf(s1[1], scale, b1b.y)) : 0.0f;
            p2[0] = (c0     < NT) ? __expf(fmaf(s0[2], scale, b2a.x)) : 0.0f;
            p2[1] = (c0 + 1 < NT) ? __expf(fmaf(s0[3], scale, b2a.y)) : 0.0f;
            p2[2] = (c0 + 8 < NT) ? __expf(fmaf(s1[2], scale, b2b.x)) : 0.0f;
            p2[3] = (c0 + 9 < NT) ? __expf(fmaf(s1[3], scale, b2b.y)) : 0.0f;

            l1 += p1[0] + p1[1] + p1[2] + p1[3];
            l2 += p2[0] + p2[1] + p2[2] + p2[3];

            // ---- publish P chunk: 4x STS.64 ----
            *(uint2*)&pw[g * LDP + 2 * t] =
                make_uint2(f2tf(p1[0]), f2tf(p1[1]));
            *(uint2*)&pw[g * LDP + 2 * t + 8] =
                make_uint2(f2tf(p1[2]), f2tf(p1[3]));
            *(uint2*)&pw[(g + 8) * LDP + 2 * t] =
                make_uint2(f2tf(p2[0]), f2tf(p2[1]));
            *(uint2*)&pw[(g + 8) * LDP + 2 * t + 8] =
                make_uint2(f2tf(p2[2]), f2tf(p2[3]));
            __syncwarp();

            // ---- P a-frags ----
            unsigned pa[2][4];
#pragma unroll
            for (int k2 = 0; k2 < 2; k2++)
                ldsm4(pa[k2][0], pa[k2][1], pa[k2][2], pa[k2][3],
                      pw_lane + (k2 * 8) * 4);

            // ---- V b-frags 2 tiles at a time + PV mma ----
#pragma unroll
            for (int cp = 0; cp < 2; cp++) {
                unsigned vb[2][2][2];
#pragma unroll
                for (int u = 0; u < 2; u++) {
                    int ct = cp * 2 + u;
                    ldsm4(vb[u][0][0], vb[u][0][1],
                          vb[u][1][0], vb[u][1][1],
                          vt_lane + (ct * 8 * LDVT + j0) * 4);
                }
#pragma unroll
                for (int u = 0; u < 2; u++)
#pragma unroll
                    for (int k2 = 0; k2 < 2; k2++)
                        mma8(o[cp * 2 + u], pa[k2], vb[u][k2]);
            }
            __syncwarp();
        }

        l1 += __shfl_xor_sync(0xffffffffu, l1, 1);
        l1 += __shfl_xor_sync(0xffffffffu, l1, 2);
        l2 += __shfl_xor_sync(0xffffffffu, l2, 1);
        l2 += __shfl_xor_sync(0xffffffffu, l2, 2);
        const float inv1 = 1.0f / l1;
        const float inv2 = 1.0f / l2;

        if (r1 < NT) {
            unsigned* c1 = g_ctx + ((size_t)win * NT + r1) * D + h * DH;
#pragma unroll
            for (int ct = 0; ct < 4; ct++)
                *(uint2*)&c1[ct * 8 + 2 * t] =
                    make_uint2(f2tf(o[ct][0] * inv1), f2tf(o[ct][1] * inv1));
        }
        if (r2 < NT) {
            unsigned* c2 = g_ctx + ((size_t)win * NT + r2) * D + h * DH;
#pragma unroll
            for (int ct = 0; ct < 4; ct++)
                *(uint2*)&c2[ct * 8 + 2 * t] =
                    make_uint2(f2tf(o[ct][2] * inv2), f2tf(o[ct][3] * inv2));
        }
    }
}

// ---------------------------------------------------------------------------
// launch
// ---------------------------------------------------------------------------
extern "C" void kernel_launch(void* const* d_in, const int* in_sizes, int n_in,
                              void* d_out, int out_size) {
    const float* x     = (const float*)d_in[0];
    const float* w_qkv = (const float*)d_in[1];
    const float* w_out = (const float*)d_in[2];
    const float* table = (const float*)d_in[3];
    float* out = (float*)d_out;

    {
        int n4x = NWIN * NT * D / 4;
        cvt_x_kernel<<<(n4x + 255) / 256, 256>>>((const float4*)x);
        int n4q = D * 3 * D / 4;
        cvt_wqkv_kernel<<<(n4q + 255) / 256, 256>>>((const float4*)w_qkv);
        int n4o = D * D / 4;
        cvt_wout_kernel<<<(n4o + 255) / 256, 256>>>((const float4*)w_out);
    }
    {
        int total = H * NT * NTB;
        bias_kernel<<<(total + 255) / 256, 256>>>(table);
    }
    {
        dim3 grid(3 * D / 128, (NWIN * NT) / 128);
        k_gemm_qkv<<<grid, 256>>>();
    }
    {
        const int smem = (NTP * LDKS + 32 * LDVT + AWARPS * 16 * LDP)
                         * (int)sizeof(unsigned);
        static int configured = -1;
        if (configured < 0) {
            cudaFuncSetAttribute(attn_kernel,
                                 cudaFuncAttributeMaxDynamicSharedMemorySize, smem);
            configured = 1;
        }
        dim3 grid(NWIN, H);
        attn_kernel<<<grid, ATHREADS, smem>>>();
    }
    {
        dim3 grid(D / 128, (NWIN * NT) / 128);
        k_gemm_out<<<grid, 256>>>(out);
    }
}

// round 8
// speedup vs baseline: 1.1094x; 1.0586x over previous
#include <cuda_runtime.h>

// ---------------------------------------------------------------------------
// MaxViT3D MHSA, tf32 tensor-core pipeline (round 8):
//   = round-3 pipeline (best known: 427us) with ONE change:
//     attention __launch_bounds__(352, 2) -> 2 CTAs/SM (22 warps, was 11)
//   - cp.async double-buffered tf32 GEMMs (cvt at fragment load)
//   - flash-style attention without online-max (logits provably bounded)
// ---------------------------------------------------------------------------

#define NWIN 128
#define NT   343
#define NTP  352          // padded to 22*16
#define NTB  352          // bias row stride (even -> aligned float2)
#define D    256
#define H    8
#define DH   32

// scratch
__device__ float g_qkv [(size_t)NWIN * NT * (3 * D)];
__device__ float g_ctx [(size_t)NWIN * NT * D];
__device__ float g_bias[(size_t)H * NT * NTB];

// ---------------------------------------------------------------------------
// helpers
// ---------------------------------------------------------------------------
__device__ __forceinline__ unsigned f2tf(float f) {
    unsigned r;
    asm("cvt.rna.tf32.f32 %0, %1;" : "=r"(r) : "f"(f));
    return r;
}

__device__ __forceinline__ void mma8(float* c, const unsigned* a, const unsigned* b) {
    asm volatile(
        "mma.sync.aligned.m16n8k8.row.col.f32.tf32.tf32.f32 "
        "{%0,%1,%2,%3},{%4,%5,%6,%7},{%8,%9},{%0,%1,%2,%3};"
        : "+f"(c[0]), "+f"(c[1]), "+f"(c[2]), "+f"(c[3])
        : "r"(a[0]), "r"(a[1]), "r"(a[2]), "r"(a[3]), "r"(b[0]), "r"(b[1]));
}

__device__ __forceinline__ unsigned smem_u32(const void* p) {
    unsigned r;
    asm("{.reg .u64 t; cvta.to.shared.u64 t, %1; cvt.u32.u64 %0, t;}"
        : "=r"(r) : "l"(p));
    return r;
}

__device__ __forceinline__ void cpa16(unsigned dst, const void* src) {
    asm volatile("cp.async.ca.shared.global [%0], [%1], 16;" :: "r"(dst), "l"(src));
}
#define CP_COMMIT() asm volatile("cp.async.commit_group;")
#define CP_WAIT0()  asm volatile("cp.async.wait_group 0;")

// ---------------------------------------------------------------------------
// bias precompute (padded row stride NTB)
// ---------------------------------------------------------------------------
__global__ void bias_kernel(const float* __restrict__ table) {
    int idx = blockIdx.x * blockDim.x + threadIdx.x;
    const int total = H * NT * NTB;
    if (idx >= total) return;
    int h = idx / (NT * NTB);
    int r = idx - h * (NT * NTB);
    int i = r / NTB;
    int j = r - i * NTB;
    float v = 0.0f;
    if (j < NT) {
        int i1 = i / 49, i2 = (i / 7) % 7, i3 = i % 7;
        int j1 = j / 49, j2 = (j / 7) % 7, j3 = j % 7;
        int rel = ((i1 - j1 + 6) * 13 + (i2 - j2 + 6)) * 13 + (i3 - j3 + 6);
        v = table[rel * H + h];
    }
    g_bias[idx] = v;
}

// ---------------------------------------------------------------------------
// tf32 GEMM, 128x128 block tile, BK=16, 8 warps of 64x32, cp.async 2-stage.
// fp32 staged; cvt.rna.tf32 at fragment load (round-3 proven config).
// ---------------------------------------------------------------------------
#define LA 20
#define LB 136

__device__ __forceinline__ void tf32_gemm_body(const float* __restrict__ A,
                                               const float* __restrict__ B,
                                               float* __restrict__ C,
                                               int N, int K) {
    __shared__ float As[2][128 * LA];
    __shared__ float Bs[2][16 * LB];

    const int tid  = threadIdx.x;
    const int warp = tid >> 5, lane = tid & 31;
    const int g = lane >> 2, t = lane & 3;
    const int wm = warp >> 2, wn = warp & 3;

    const int rowBase = blockIdx.y * 128;
    const int colBase = blockIdx.x * 128;

    float acc[4][4][4];
#pragma unroll
    for (int mt = 0; mt < 4; mt++)
#pragma unroll
        for (int nt = 0; nt < 4; nt++)
#pragma unroll
            for (int i = 0; i < 4; i++) acc[mt][nt][i] = 0.0f;

    auto loadTile = [&](int buf, int k0) {
#pragma unroll
        for (int i = 0; i < 2; i++) {
            int c = tid + i * 256;
            int row = c >> 2, q = (c & 3) * 4;
            cpa16(smem_u32(&As[buf][row * LA + q]),
                  A + (size_t)(rowBase + row) * K + k0 + q);
        }
#pragma unroll
        for (int i = 0; i < 2; i++) {
            int c = tid + i * 256;
            int row = c >> 5, col = (c & 31) * 4;
            cpa16(smem_u32(&Bs[buf][row * LB + col]),
                  B + (size_t)(k0 + row) * N + colBase + col);
        }
    };

    loadTile(0, 0);
    CP_COMMIT();

    const int iters = K / 16;
    for (int it = 0; it < iters; it++) {
        CP_WAIT0();
        __syncthreads();
        if (it + 1 < iters) {
            loadTile((it + 1) & 1, (it + 1) * 16);
            CP_COMMIT();
        }
        const float* Ab = As[it & 1];
        const float* Bb = Bs[it & 1];
#pragma unroll
        for (int ks = 0; ks < 16; ks += 8) {
            unsigned a[4][4], b[4][2];
#pragma unroll
            for (int mt = 0; mt < 4; mt++) {
                int r = wm * 64 + mt * 16;
                a[mt][0] = f2tf(Ab[(r + g)     * LA + ks + t]);
                a[mt][1] = f2tf(Ab[(r + g + 8) * LA + ks + t]);
                a[mt][2] = f2tf(Ab[(r + g)     * LA + ks + t + 4]);
                a[mt][3] = f2tf(Ab[(r + g + 8) * LA + ks + t + 4]);
            }
#pragma unroll
            for (int nt = 0; nt < 4; nt++) {
                int cb = wn * 32 + nt * 8;
                b[nt][0] = f2tf(Bb[(ks + t)     * LB + cb + g]);
                b[nt][1] = f2tf(Bb[(ks + t + 4) * LB + cb + g]);
            }
#pragma unroll
            for (int mt = 0; mt < 4; mt++)
#pragma unroll
                for (int nt = 0; nt < 4; nt++) mma8(acc[mt][nt], a[mt], b[nt]);
        }
    }

#pragma unroll
    for (int mt = 0; mt < 4; mt++) {
#pragma unroll
        for (int nt = 0; nt < 4; nt++) {
            int r = rowBase + wm * 64 + mt * 16 + g;
            int c = colBase + wn * 32 + nt * 8 + 2 * t;
            *(float2*)(C + (size_t)r * N + c) =
                make_float2(acc[mt][nt][0], acc[mt][nt][1]);
            *(float2*)(C + (size_t)(r + 8) * N + c) =
                make_float2(acc[mt][nt][2], acc[mt][nt][3]);
        }
    }
}

__global__ __launch_bounds__(256)
void k_gemm_qkv(const float* __restrict__ x, const float* __restrict__ w) {
    tf32_gemm_body(x, w, g_qkv, 3 * D, D);
}

__global__ __launch_bounds__(256)
void k_gemm_out(const float* __restrict__ w, float* __restrict__ out) {
    tf32_gemm_body(g_ctx, w, out, D, D);
}

// ---------------------------------------------------------------------------
// attention: block = (window, head), 11 warps, 2 q-tiles/warp,
// scalar-LDS fragment loads (round-3 body), now 2 CTAs/SM.
// ---------------------------------------------------------------------------
#define LDKS 36
#define LDVT 356
#define LDP  20
#define AWARPS 11
#define ATHREADS (AWARPS * 32)

__global__ __launch_bounds__(ATHREADS, 2)
void attn_kernel() {
    const int win = blockIdx.x;
    const int h   = blockIdx.y;

    extern __shared__ unsigned sm[];
    unsigned* ks = sm;
    unsigned* vt = ks + NTP * LDKS;
    unsigned* ps = vt + 32 * LDVT;

    const int tid  = threadIdx.x;
    const int warp = tid >> 5, lane = tid & 31;
    const int g = lane >> 2, t = lane & 3;

    const float* base = g_qkv + (size_t)win * NT * (3 * D);

    for (int idx = tid; idx < NTP * DH; idx += ATHREADS) {
        int j = idx >> 5, c = idx & 31;
        float kv = 0.0f, vv = 0.0f;
        if (j < NT) {
            const float* row = base + (size_t)j * (3 * D) + h * DH;
            kv = row[D + c];
            vv = row[2 * D + c];
        }
        ks[j * LDKS + c] = f2tf(kv);
        vt[c * LDVT + j] = f2tf(vv);
    }
    __syncthreads();

    const float scale = 0.17677669529663687f;
    const float* bh = g_bias + (size_t)h * NT * NTB;
    unsigned* pw = ps + warp * 16 * LDP;

    for (int qt = warp; qt < 22; qt += AWARPS) {
        const int i0 = qt * 16;
        const int r1 = i0 + g, r2 = r1 + 8;
        const int r1c = r1 < NT ? r1 : NT - 1;
        const int r2c = r2 < NT ? r2 : NT - 1;

        unsigned qa[4][4];
        const float* qp = base + h * DH;
#pragma unroll
        for (int kq = 0; kq < 4; kq++) {
            qa[kq][0] = f2tf(qp[(size_t)r1c * (3 * D) + kq * 8 + t]);
            qa[kq][1] = f2tf(qp[(size_t)r2c * (3 * D) + kq * 8 + t]);
            qa[kq][2] = f2tf(qp[(size_t)r1c * (3 * D) + kq * 8 + t + 4]);
            qa[kq][3] = f2tf(qp[(size_t)r2c * (3 * D) + kq * 8 + t + 4]);
        }

        float o[4][4];
#pragma unroll
        for (int ct = 0; ct < 4; ct++)
#pragma unroll
            for (int i = 0; i < 4; i++) o[ct][i] = 0.0f;
        float l1 = 0.0f, l2 = 0.0f;

        const float* b1p = bh + (size_t)r1c * NTB;
        const float* b2p = bh + (size_t)r2c * NTB;

        for (int cc = 0; cc < 22; cc++) {
            const int j0 = cc * 16;

            float s0[4] = {0, 0, 0, 0}, s1[4] = {0, 0, 0, 0};
#pragma unroll
            for (int kq = 0; kq < 4; kq++) {
                unsigned b0[2], b1[2];
                b0[0] = ks[(j0 + g)     * LDKS + kq * 8 + t];
                b0[1] = ks[(j0 + g)     * LDKS + kq * 8 + t + 4];
                b1[0] = ks[(j0 + 8 + g) * LDKS + kq * 8 + t];
                b1[1] = ks[(j0 + 8 + g) * LDKS + kq * 8 + t + 4];
                mma8(s0, qa[kq], b0);
                mma8(s1, qa[kq], b1);
            }

            const int c0 = j0 + 2 * t;
            float2 b1a = *(const float2*)(b1p + c0);
            float2 b1b = *(const float2*)(b1p + c0 + 8);
            float2 b2a = *(const float2*)(b2p + c0);
            float2 b2b = *(const float2*)(b2p + c0 + 8);

            float p1[4], p2[4];
            p1[0] = (c0     < NT) ? __expf(fmaf(s0[0], scale, b1a.x)) : 0.0f;
            p1[1] = (c0 + 1 < NT) ? __expf(fmaf(s0[1], scale, b1a.y)) : 0.0f;
            p1[2] = (c0 + 8 < NT) ? __expf(fmaf(s1[0], scale, b1b.x)) : 0.0f;
            p1[3] = (c0 + 9 < NT) ? __expf(fmaf(s1[1], scale, b1b.y)) : 0.0f;
            p2[0] = (c0     < NT) ? __expf(fmaf(s0[2], scale, b2a.x)) : 0.0f;
            p2[1] = (c0 + 1 < NT) ? __expf(fmaf(s0[3], scale, b2a.y)) : 0.0f;
            p2[2] = (c0 + 8 < NT) ? __expf(fmaf(s1[2], scale, b2b.x)) : 0.0f;
            p2[3] = (c0 + 9 < NT) ? __expf(fmaf(s1[3], scale, b2b.y)) : 0.0f;

            l1 += p1[0] + p1[1] + p1[2] + p1[3];
            l2 += p2[0] + p2[1] + p2[2] + p2[3];

            pw[g * LDP + 2 * t]           = f2tf(p1[0]);
            pw[g * LDP + 2 * t + 1]       = f2tf(p1[1]);
            pw[g * LDP + 2 * t + 8]       = f2tf(p1[2]);
            pw[g * LDP + 2 * t + 9]       = f2tf(p1[3]);
            pw[(g + 8) * LDP + 2 * t]     = f2tf(p2[0]);
            pw[(g + 8) * LDP + 2 * t + 1] = f2tf(p2[1]);
            pw[(g + 8) * LDP + 2 * t + 8] = f2tf(p2[2]);
            pw[(g + 8) * LDP + 2 * t + 9] = f2tf(p2[3]);
            __syncwarp();

#pragma unroll
            for (int k2 = 0; k2 < 2; k2++) {
                int kb = k2 * 8;
                unsigned a[4];
                a[0] = pw[g * LDP + kb + t];
                a[1] = pw[(g + 8) * LDP + kb + t];
                a[2] = pw[g * LDP + kb + t + 4];
                a[3] = pw[(g + 8) * LDP + kb + t + 4];
#pragma unroll
                for (int ct = 0; ct < 4; ct++) {
                    unsigned b[2];
                    b[0] = vt[(ct * 8 + g) * LDVT + j0 + kb + t];
                    b[1] = vt[(ct * 8 + g) * LDVT + j0 + kb + t + 4];
                    mma8(o[ct], a, b);
                }
            }
            __syncwarp();
        }

        l1 += __shfl_xor_sync(0xffffffffu, l1, 1);
        l1 += __shfl_xor_sync(0xffffffffu, l1, 2);
        l2 += __shfl_xor_sync(0xffffffffu, l2, 1);
        l2 += __shfl_xor_sync(0xffffffffu, l2, 2);
        const float inv1 = 1.0f / l1;
        const float inv2 = 1.0f / l2;

        if (r1 < NT) {
            float* c1 = g_ctx + ((size_t)win * NT + r1) * D + h * DH;
#pragma unroll
            for (int ct = 0; ct < 4; ct++)
                *(float2*)(c1 + ct * 8 + 2 * t) =
                    make_float2(o[ct][0] * inv1, o[ct][1] * inv1);
        }
        if (r2 < NT) {
            float* c2 = g_ctx + ((size_t)win * NT + r2) * D + h * DH;
#pragma unroll
            for (int ct = 0; ct < 4; ct++)
                *(float2*)(c2 + ct * 8 + 2 * t) =
                    make_float2(o[ct][2] * inv2, o[ct][3] * inv2);
        }
    }
}

// ---------------------------------------------------------------------------
// launch
// ---------------------------------------------------------------------------
extern "C" void kernel_launch(void* const* d_in, const int* in_sizes, int n_in,
                              void* d_out, int out_size) {
    const float* x     = (const float*)d_in[0];
    const float* w_qkv = (const float*)d_in[1];
    const float* w_out = (const float*)d_in[2];
    const float* table = (const float*)d_in[3];
    float* out = (float*)d_out;

    {
        int total = H * NT * NTB;
        bias_kernel<<<(total + 255) / 256, 256>>>(table);
    }
    {
        dim3 grid(3 * D / 128, (NWIN * NT) / 128);   // (6, 343)
        k_gemm_qkv<<<grid, 256>>>(x, w_qkv);
    }
    {
        const int smem = (NTP * LDKS + 32 * LDVT + AWARPS * 16 * LDP)
                         * (int)sizeof(unsigned);
        static int configured = -1;
        if (configured < 0) {
            cudaFuncSetAttribute(attn_kernel,
                                 cudaFuncAttributeMaxDynamicSharedMemorySize, smem);
            configured = 1;
        }
        dim3 grid(NWIN, H);
        attn_kernel<<<grid, ATHREADS, smem>>>();
    }
    {
        dim3 grid(D / 128, (NWIN * NT) / 128);       // (2, 343)
        k_gemm_out<<<grid, 256>>>(w_out, out);
    }
}

// round 10
// speedup vs baseline: 1.5742x; 1.4189x over previous
#include <cuda_runtime.h>
#include <cuda_fp16.h>
#include <cstdint>

// ---------------------------------------------------------------------------
// MaxViT3D MHSA (round 10): full fp16 mma pipeline (fp32 accumulate).
//   fp16 has the SAME 11-bit significand as tf32 -> accuracy preserved,
//   but m16n8k16 does 2x FLOP/instruction and operands are half the bytes.
//   (tcgen05 unavailable: harness lowers via compute_103, no 'a' features.)
//   - qkv & out GEMMs: 128x128 tile, BK=32, cp.async double-buffered
//   - attention: round-3 structure, fp16 fragments, no online-max
// ---------------------------------------------------------------------------

#define NWIN 128
#define NT   343
#define NTP  352
#define NTB  352
#define D    256
#define H    8
#define DH   32

// scratch
__device__ __half g_qkvh [(size_t)NWIN * NT * (3 * D)];
__device__ __half g_ctxh [(size_t)NWIN * NT * D];
__device__ __half g_xh   [(size_t)NWIN * NT * D];
__device__ __half g_wqkvTh[(size_t)(3 * D) * D];   // W_qkv^T [768][256] K-major
__device__ __half g_woutTh[(size_t)D * D];         // W_out^T [256][256] K-major
__device__ float  g_bias [(size_t)H * NT * NTB];

// ---------------------------------------------------------------------------
// helpers
// ---------------------------------------------------------------------------
__device__ __forceinline__ void mma16(float* c, const unsigned* a,
                                      unsigned b0, unsigned b1) {
    asm volatile(
        "mma.sync.aligned.m16n8k16.row.col.f32.f16.f16.f32 "
        "{%0,%1,%2,%3},{%4,%5,%6,%7},{%8,%9},{%0,%1,%2,%3};"
        : "+f"(c[0]), "+f"(c[1]), "+f"(c[2]), "+f"(c[3])
        : "r"(a[0]), "r"(a[1]), "r"(a[2]), "r"(a[3]), "r"(b0), "r"(b1));
}

__device__ __forceinline__ unsigned smem_u32(const void* p) {
    unsigned r;
    asm("{.reg .u64 t; cvta.to.shared.u64 t, %1; cvt.u32.u64 %0, t;}"
        : "=r"(r) : "l"(p));
    return r;
}

__device__ __forceinline__ void cpa16(unsigned dst, const void* src) {
    asm volatile("cp.async.ca.shared.global [%0], [%1], 16;" :: "r"(dst), "l"(src));
}
#define CP_COMMIT() asm volatile("cp.async.commit_group;")

// ---------------------------------------------------------------------------
// prep kernels (device globals referenced from device code only)
// ---------------------------------------------------------------------------
__global__ void cvt_x_kernel(const float4* __restrict__ src) {
    int i = blockIdx.x * blockDim.x + threadIdx.x;
    const int n4 = NWIN * NT * D / 4;
    if (i < n4) {
        float4 v = src[i];
        __half2 h0 = __floats2half2_rn(v.x, v.y);
        __half2 h1 = __floats2half2_rn(v.z, v.w);
        ((uint2*)g_xh)[i] = make_uint2(*(unsigned*)&h0, *(unsigned*)&h1);
    }
}
__global__ void prep_wqkv_kernel(const float* __restrict__ w) {
    int idx = blockIdx.x * blockDim.x + threadIdx.x;   // over [768][256]
    if (idx < 3 * D * D) {
        int n = idx >> 8, k = idx & 255;
        g_wqkvTh[idx] = __float2half_rn(w[k * (3 * D) + n]);
    }
}
__global__ void prep_wout_kernel(const float* __restrict__ w) {
    int idx = blockIdx.x * blockDim.x + threadIdx.x;   // over [256][256]
    if (idx < D * D) {
        int n = idx >> 8, k = idx & 255;
        g_woutTh[idx] = __float2half_rn(w[k * D + n]);
    }
}

// ---------------------------------------------------------------------------
// bias precompute
// ---------------------------------------------------------------------------
__global__ void bias_kernel(const float* __restrict__ table) {
    int idx = blockIdx.x * blockDim.x + threadIdx.x;
    const int total = H * NT * NTB;
    if (idx >= total) return;
    int h = idx / (NT * NTB);
    int r = idx - h * (NT * NTB);
    int i = r / NTB;
    int j = r - i * NTB;
    float v = 0.0f;
    if (j < NT) {
        int i1 = i / 49, i2 = (i / 7) % 7, i3 = i % 7;
        int j1 = j / 49, j2 = (j / 7) % 7, j3 = j % 7;
        int rel = ((i1 - j1 + 6) * 13 + (i2 - j2 + 6)) * 13 + (i3 - j3 + 6);
        v = table[rel * H + h];
    }
    g_bias[idx] = v;
}

// ---------------------------------------------------------------------------
// fp16 GEMM: C[M,Ngl] = A[M,256] * B^T (B stored [Ngl][256] K-major halfs).
// 128x128 tile, BK=32, 8 warps of 64x32, cp.async double-buffered.
// smem rows: 40 halfs (80B) -> conflict-free half2 fragment loads.
// ---------------------------------------------------------------------------
#define LGH 40   // smem row stride in halfs

__device__ __forceinline__ void stage32(unsigned dstBase,
                                        const __half* __restrict__ gsrc) {
    const int tid = threadIdx.x;
#pragma unroll
    for (int i = 0; i < 2; i++) {
        int id  = tid + i * 256;
        int row = id >> 2;
        int gc  = (id & 3) * 8;            // 8 halfs = 16B granule
        cpa16(dstBase + (unsigned)(row * LGH + gc) * 2,
              gsrc + (size_t)row * 256 + gc);
    }
}

template <bool HALF_OUT>
__device__ __forceinline__ void fp16_gemm_body(const __half* __restrict__ Ag,
                                               const __half* __restrict__ Bg,
                                               float* __restrict__ Cf,
                                               __half* __restrict__ Ch,
                                               int Ngl) {
    __shared__ __half As[2][128 * LGH];
    __shared__ __half Bs[2][128 * LGH];

    const int tid  = threadIdx.x;
    const int warp = tid >> 5, lane = tid & 31;
    const int g = lane >> 2, t = lane & 3;
    const int wm = warp >> 2, wn = warp & 3;

    const int rowBase = blockIdx.y * 128;
    const int colBase = blockIdx.x * 128;

    const __half* Ab = Ag + (size_t)rowBase * 256;
    const __half* Bb = Bg + (size_t)colBase * 256;

    const unsigned asb0 = smem_u32(&As[0][0]);
    const unsigned bsb0 = smem_u32(&Bs[0][0]);
    const unsigned bufBytes = 128 * LGH * 2;

    float acc[4][4][4];
#pragma unroll
    for (int mt = 0; mt < 4; mt++)
#pragma unroll
        for (int nt = 0; nt < 4; nt++)
#pragma unroll
            for (int i = 0; i < 4; i++) acc[mt][nt][i] = 0.0f;

    stage32(asb0, Ab);
    stage32(bsb0, Bb);
    CP_COMMIT();

    const int iters = 256 / 32;   // 8
    for (int it = 0; it < iters; it++) {
        asm volatile("cp.async.wait_group 0;" ::: "memory");
        __syncthreads();
        if (it + 1 < iters) {
            int nb = (it + 1) & 1;
            stage32(asb0 + nb * bufBytes, Ab + (it + 1) * 32);
            stage32(bsb0 + nb * bufBytes, Bb + (it + 1) * 32);
            CP_COMMIT();
        }
        const __half* Abs = As[it & 1];
        const __half* Bbs = Bs[it & 1];

#pragma unroll
        for (int ks = 0; ks < 32; ks += 16) {
            unsigned a[4][4], b[4][2];
#pragma unroll
            for (int mt = 0; mt < 4; mt++) {
                int r = wm * 64 + mt * 16;
                a[mt][0] = *(const unsigned*)&Abs[(r + g)     * LGH + ks + 2 * t];
                a[mt][1] = *(const unsigned*)&Abs[(r + g + 8) * LGH + ks + 2 * t];
                a[mt][2] = *(const unsigned*)&Abs[(r + g)     * LGH + ks + 2 * t + 8];
                a[mt][3] = *(const unsigned*)&Abs[(r + g + 8) * LGH + ks + 2 * t + 8];
            }
#pragma unroll
            for (int nt = 0; nt < 4; nt++) {
                int cb = wn * 32 + nt * 8;
                b[nt][0] = *(const unsigned*)&Bbs[(cb + g) * LGH + ks + 2 * t];
                b[nt][1] = *(const unsigned*)&Bbs[(cb + g) * LGH + ks + 2 * t + 8];
            }
#pragma unroll
            for (int mt = 0; mt < 4; mt++)
#pragma unroll
                for (int nt = 0; nt < 4; nt++)
                    mma16(acc[mt][nt], a[mt], b[nt][0], b[nt][1]);
        }
    }

#pragma unroll
    for (int mt = 0; mt < 4; mt++) {
#pragma unroll
        for (int nt = 0; nt < 4; nt++) {
            int r = rowBase + wm * 64 + mt * 16 + g;
            int c = colBase + wn * 32 + nt * 8 + 2 * t;
            if (HALF_OUT) {
                __half2 h0 = __floats2half2_rn(acc[mt][nt][0], acc[mt][nt][1]);
                __half2 h1 = __floats2half2_rn(acc[mt][nt][2], acc[mt][nt][3]);
                *(__half2*)(Ch + (size_t)r * Ngl + c)       = h0;
                *(__half2*)(Ch + (size_t)(r + 8) * Ngl + c) = h1;
            } else {
                *(float2*)(Cf + (size_t)r * Ngl + c) =
                    make_float2(acc[mt][nt][0], acc[mt][nt][1]);
                *(float2*)(Cf + (size_t)(r + 8) * Ngl + c) =
                    make_float2(acc[mt][nt][2], acc[mt][nt][3]);
            }
        }
    }
}

__global__ __launch_bounds__(256)
void k_gemm_qkv() {
    fp16_gemm_body<true>(g_xh, g_wqkvTh, nullptr, g_qkvh, 3 * D);
}

__global__ __launch_bounds__(256)
void k_gemm_out(float* __restrict__ out) {
    fp16_gemm_body<false>(g_ctxh, g_woutTh, out, nullptr, D);
}

// ---------------------------------------------------------------------------
// attention: block = (window, head), 11 warps, fp16 fragments.
// ks [NTP][40] halfs, vt [32][360] halfs, pw [16][24] halfs per warp.
// ---------------------------------------------------------------------------
#define LDKH 40
#define LDVH 360
#define LDPH 24
#define AWARPS 11
#define ATHREADS (AWARPS * 32)

__global__ __launch_bounds__(ATHREADS)
void attn_kernel() {
    const int win = blockIdx.x;
    const int h   = blockIdx.y;

    extern __shared__ __half smh[];
    __half* ks = smh;                         // NTP*LDKH
    __half* vt = ks + NTP * LDKH;             // 32*LDVH
    __half* pb = vt + 32 * LDVH;              // AWARPS*16*LDPH

    const int tid  = threadIdx.x;
    const int warp = tid >> 5, lane = tid & 31;
    const int g = lane >> 2, t = lane & 3;

    const __half* baseh = g_qkvh + (size_t)win * NT * (3 * D);

    // stage K [j][c] and V^T [c][j] (zero-pad j >= NT)
    for (int idx = tid; idx < NTP * DH; idx += ATHREADS) {
        int j = idx >> 5, c = idx & 31;
        __half kv = __float2half_rn(0.0f), vv = kv;
        if (j < NT) {
            const __half* row = baseh + (size_t)j * (3 * D) + h * DH;
            kv = row[D + c];
            vv = row[2 * D + c];
        }
        ks[j * LDKH + c] = kv;
        vt[c * LDVH + j] = vv;
    }
    __syncthreads();

    const float scale = 0.17677669529663687f;   // 1/sqrt(32)
    const float* bh = g_bias + (size_t)h * NT * NTB;
    __half* pw = pb + warp * 16 * LDPH;

    for (int qt = warp; qt < 22; qt += AWARPS) {
        const int i0 = qt * 16;
        const int r1 = i0 + g, r2 = r1 + 8;
        const int r1c = r1 < NT ? r1 : NT - 1;
        const int r2c = r2 < NT ? r2 : NT - 1;

        // Q fragments: 2 k-steps (DH=32 = 2 x k16)
        unsigned qa[2][4];
        const __half* q1p = baseh + (size_t)r1c * (3 * D) + h * DH;
        const __half* q2p = baseh + (size_t)r2c * (3 * D) + h * DH;
#pragma unroll
        for (int kk = 0; kk < 2; kk++) {
            qa[kk][0] = *(const unsigned*)(q1p + kk * 16 + 2 * t);
            qa[kk][1] = *(const unsigned*)(q2p + kk * 16 + 2 * t);
            qa[kk][2] = *(const unsigned*)(q1p + kk * 16 + 2 * t + 8);
            qa[kk][3] = *(const unsigned*)(q2p + kk * 16 + 2 * t + 8);
        }

        float o[4][4];
#pragma unroll
        for (int ct = 0; ct < 4; ct++)
#pragma unroll
            for (int i = 0; i < 4; i++) o[ct][i] = 0.0f;
        float l1 = 0.0f, l2 = 0.0f;

        const float* b1p = bh + (size_t)r1c * NTB;
        const float* b2p = bh + (size_t)r2c * NTB;

        for (int cc = 0; cc < 22; cc++) {
            const int j0 = cc * 16;

            // ---- QK^T: 16x16 S chunk, 4 mmas ----
            float s0[4] = {0, 0, 0, 0}, s1[4] = {0, 0, 0, 0};
#pragma unroll
            for (int kk = 0; kk < 2; kk++) {
                unsigned b0a = *(const unsigned*)&ks[(j0 + g)     * LDKH + kk * 16 + 2 * t];
                unsigned b0b = *(const unsigned*)&ks[(j0 + g)     * LDKH + kk * 16 + 2 * t + 8];
                unsigned b1a = *(const unsigned*)&ks[(j0 + 8 + g) * LDKH + kk * 16 + 2 * t];
                unsigned b1b = *(const unsigned*)&ks[(j0 + 8 + g) * LDKH + kk * 16 + 2 * t + 8];
                mma16(s0, qa[kk], b0a, b0b);
                mma16(s1, qa[kk], b1a, b1b);
            }

            // ---- bias + exp (no max: logits bounded) ----
            const int c0 = j0 + 2 * t;
            float2 b1a = *(const float2*)(b1p + c0);
            float2 b1b = *(const float2*)(b1p + c0 + 8);
            float2 b2a = *(const float2*)(b2p + c0);
            float2 b2b = *(const float2*)(b2p + c0 + 8);

            float p1[4], p2[4];
            p1[0] = (c0     < NT) ? __expf(fmaf(s0[0], scale, b1a.x)) : 0.0f;
            p1[1] = (c0 + 1 < NT) ? __expf(fmaf(s0[1], scale, b1a.y)) : 0.0f;
            p1[2] = (c0 + 8 < NT) ? __expf(fmaf(s1[0], scale, b1b.x)) : 0.0f;
            p1[3] = (c0 + 9 < NT) ? __expf(fmaf(s1[1], scale, b1b.y)) : 0.0f;
            p2[0] = (c0     < NT) ? __expf(fmaf(s0[2], scale, b2a.x)) : 0.0f;
            p2[1] = (c0 + 1 < NT) ? __expf(fmaf(s0[3], scale, b2a.y)) : 0.0f;
            p2[2] = (c0 + 8 < NT) ? __expf(fmaf(s1[2], scale, b2b.x)) : 0.0f;
            p2[3] = (c0 + 9 < NT) ? __expf(fmaf(s1[3], scale, b2b.y)) : 0.0f;

            l1 += p1[0] + p1[1] + p1[2] + p1[3];
            l2 += p2[0] + p2[1] + p2[2] + p2[3];

            // ---- publish P chunk as half2 (4 STS.32) ----
            *(__half2*)&pw[g * LDPH + 2 * t]           = __floats2half2_rn(p1[0], p1[1]);
            *(__half2*)&pw[g * LDPH + 2 * t + 8]       = __floats2half2_rn(p1[2], p1[3]);
            *(__half2*)&pw[(g + 8) * LDPH + 2 * t]     = __floats2half2_rn(p2[0], p2[1]);
            *(__half2*)&pw[(g + 8) * LDPH + 2 * t + 8] = __floats2half2_rn(p2[2], p2[3]);
            __syncwarp();

            // ---- PV: k16 = whole chunk, 4 mmas ----
            unsigned pa[4];
            pa[0] = *(const unsigned*)&pw[g * LDPH + 2 * t];
            pa[1] = *(const unsigned*)&pw[(g + 8) * LDPH + 2 * t];
            pa[2] = *(const unsigned*)&pw[g * LDPH + 2 * t + 8];
            pa[3] = *(const unsigned*)&pw[(g + 8) * LDPH + 2 * t + 8];
#pragma unroll
            for (int ct = 0; ct < 4; ct++) {
                unsigned b0 = *(const unsigned*)&vt[(ct * 8 + g) * LDVH + j0 + 2 * t];
                unsigned b1 = *(const unsigned*)&vt[(ct * 8 + g) * LDVH + j0 + 2 * t + 8];
                mma16(o[ct], pa, b0, b1);
            }
            __syncwarp();
        }

        l1 += __shfl_xor_sync(0xffffffffu, l1, 1);
        l1 += __shfl_xor_sync(0xffffffffu, l1, 2);
        l2 += __shfl_xor_sync(0xffffffffu, l2, 1);
        l2 += __shfl_xor_sync(0xffffffffu, l2, 2);
        const float inv1 = 1.0f / l1;
        const float inv2 = 1.0f / l2;

        // ctx as half (out-proj consumes directly)
        if (r1 < NT) {
            __half* c1 = g_ctxh + ((size_t)win * NT + r1) * D + h * DH;
#pragma unroll
            for (int ct = 0; ct < 4; ct++)
                *(__half2*)(c1 + ct * 8 + 2 * t) =
                    __floats2half2_rn(o[ct][0] * inv1, o[ct][1] * inv1);
        }
        if (r2 < NT) {
            __half* c2 = g_ctxh + ((size_t)win * NT + r2) * D + h * DH;
#pragma unroll
            for (int ct = 0; ct < 4; ct++)
                *(__half2*)(c2 + ct * 8 + 2 * t) =
                    __floats2half2_rn(o[ct][2] * inv2, o[ct][3] * inv2);
        }
    }
}

// ---------------------------------------------------------------------------
// launch
// ---------------------------------------------------------------------------
extern "C" void kernel_launch(void* const* d_in, const int* in_sizes, int n_in,
                              void* d_out, int out_size) {
    const float* x     = (const float*)d_in[0];
    const float* w_qkv = (const float*)d_in[1];
    const float* w_out = (const float*)d_in[2];
    const float* table = (const float*)d_in[3];
    float* out = (float*)d_out;

    const int attn_smem = (NTP * LDKH + 32 * LDVH + AWARPS * 16 * LDPH)
                          * (int)sizeof(__half);   // 59648 B
    static int configured = -1;
    if (configured < 0) {
        cudaFuncSetAttribute(attn_kernel,
                             cudaFuncAttributeMaxDynamicSharedMemorySize, attn_smem);
        configured = 1;
    }

    {   // prep: fp16 conversions + weight transposes + bias
        int n4x = NWIN * NT * D / 4;
        cvt_x_kernel<<<(n4x + 255) / 256, 256>>>((const float4*)x);
        int nq = 3 * D * D;
        prep_wqkv_kernel<<<(nq + 255) / 256, 256>>>(w_qkv);
        int no = D * D;
        prep_wout_kernel<<<(no + 255) / 256, 256>>>(w_out);
        int total = H * NT * NTB;
        bias_kernel<<<(total + 255) / 256, 256>>>(table);
    }
    {   // qkv: M=43904, N=768, K=256
        dim3 grid(3 * D / 128, (NWIN * NT) / 128);   // (6, 343)
        k_gemm_qkv<<<grid, 256>>>();
    }
    {
        dim3 grid(NWIN, H);
        attn_kernel<<<grid, ATHREADS, attn_smem>>>();
    }
    {   // out: M=43904, N=256, K=256
        dim3 grid(D / 128, (NWIN * NT) / 128);       // (2, 343)
        k_gemm_out<<<grid, 256>>>(out);
    }
}